// round 1
// baseline (speedup 1.0000x reference)
#include <cuda_runtime.h>
#include <cuda_bf16.h>
#include <math.h>

// Scratch (no device allocation allowed). Sized with headroom over R=2048.
__device__ float g_cls[4096];
__device__ float g_per_roi[4096];

// ---------------------------------------------------------------------------
// Kernel 1: per-row -log_softmax(class_logit)[label]  -> g_cls[row]
// One warp per row (C=81 columns).
// ---------------------------------------------------------------------------
__global__ void cls_rows_kernel(const float* __restrict__ logits,
                                const int* __restrict__ label,
                                float* __restrict__ out_rows,
                                int R, int C) {
    int warp = (blockIdx.x * blockDim.x + threadIdx.x) >> 5;
    int lane = threadIdx.x & 31;
    if (warp >= R) return;
    const float* row = logits + (size_t)warp * C;

    float mx = -INFINITY;
    for (int c = lane; c < C; c += 32) mx = fmaxf(mx, row[c]);
    #pragma unroll
    for (int o = 16; o; o >>= 1) mx = fmaxf(mx, __shfl_xor_sync(0xFFFFFFFFu, mx, o));

    float s = 0.0f;
    for (int c = lane; c < C; c += 32) s += expf(row[c] - mx);
    #pragma unroll
    for (int o = 16; o; o >>= 1) s += __shfl_xor_sync(0xFFFFFFFFu, s, o);

    if (lane == 0) {
        float lse = mx + logf(s);
        float x = row[label[warp]];
        out_rows[warp] = lse - x;   // = -logp[label]
    }
}

// ---------------------------------------------------------------------------
// Kernel 2: per-RoI mask BCE mean (roi_align 1-sample bilinear target).
// One block (256 threads) per RoI. Deterministic fixed-tree reduction.
// ---------------------------------------------------------------------------
__global__ void mask_kernel(const float* __restrict__ mask_logit,
                            const float* __restrict__ proposal,
                            const float* __restrict__ gt_mask,
                            const int* __restrict__ matched_idx,
                            const int* __restrict__ label,
                            float* __restrict__ per_roi,
                            int C, int Mo, int Hh, int Ww) {
    int r = blockIdx.x;
    __shared__ float sh[8];

    int lab = label[r];
    int b   = matched_idx[r];
    float x1 = proposal[r * 4 + 0];
    float y1 = proposal[r * 4 + 1];
    float x2 = proposal[r * 4 + 2];
    float y2 = proposal[r * 4 + 3];
    float sx = (x2 - x1) / (float)Mo;
    float sy = (y2 - y1) / (float)Mo;

    int P = Mo * Mo;
    const float* sel = mask_logit + ((size_t)r * C + lab) * P;
    const float* fm  = gt_mask + (size_t)b * Hh * Ww;

    float acc = 0.0f;
    for (int p = threadIdx.x; p < P; p += blockDim.x) {
        int iy = p / Mo;
        int ix = p - iy * Mo;
        float x = x1 + ((float)ix + 0.5f) * sx;
        float y = y1 + ((float)iy + 0.5f) * sy;

        float t = 0.0f;
        if (x > -1.0f && x < (float)Ww && y > -1.0f && y < (float)Hh) {
            float xc = fminf(fmaxf(x, 0.0f), (float)(Ww - 1));
            float yc = fminf(fmaxf(y, 0.0f), (float)(Hh - 1));
            int x0 = (int)floorf(xc);
            int y0 = (int)floorf(yc);
            int x1i = min(x0 + 1, Ww - 1);
            int y1i = min(y0 + 1, Hh - 1);
            float lx = xc - (float)x0;
            float ly = yc - (float)y0;
            const float* r0 = fm + (size_t)y0  * Ww;
            const float* r1 = fm + (size_t)y1i * Ww;
            float v00 = __ldg(r0 + x0);
            float v01 = __ldg(r0 + x1i);
            float v10 = __ldg(r1 + x0);
            float v11 = __ldg(r1 + x1i);
            float top = v00 * (1.0f - lx) + v01 * lx;
            float bot = v10 * (1.0f - lx) + v11 * lx;
            t = top * (1.0f - ly) + bot * ly;
        }
        float s = sel[p];
        // bce = max(s,0) - s*t + log1p(exp(-|s|))
        acc += fmaxf(s, 0.0f) - s * t + log1pf(__expf(-fabsf(s)));
    }

    // warp reduce
    #pragma unroll
    for (int o = 16; o; o >>= 1) acc += __shfl_xor_sync(0xFFFFFFFFu, acc, o);
    int lane = threadIdx.x & 31;
    int w    = threadIdx.x >> 5;
    if (lane == 0) sh[w] = acc;
    __syncthreads();
    if (w == 0) {
        float v = (lane < 8) ? sh[lane] : 0.0f;
        #pragma unroll
        for (int o = 4; o; o >>= 1) v += __shfl_xor_sync(0xFFFFFFFFu, v, o);
        if (lane == 0) per_roi[r] = v / (float)P;
    }
}

// ---------------------------------------------------------------------------
// Kernel 3: finalize. One block: cls mean, box smooth-L1, segment mean per gt.
// ---------------------------------------------------------------------------
__global__ void finalize_kernel(const float* __restrict__ cls_rows,
                                const float* __restrict__ box_regression,
                                const float* __restrict__ regression_target,
                                const float* __restrict__ per_roi,
                                const int* __restrict__ matched_idx,
                                const int* __restrict__ label,
                                float* __restrict__ out,
                                int R, int C, int G, int num_pos) {
    extern __shared__ float smem[];
    float* bins = smem;           // G
    float* cnts = smem + G;       // G
    __shared__ float red[8];

    int tid = threadIdx.x;
    int nthreads = blockDim.x;

    for (int g = tid; g < G; g += nthreads) { bins[g] = 0.0f; cnts[g] = 0.0f; }
    __syncthreads();

    // cls sum
    float cls_acc = 0.0f;
    for (int r = tid; r < R; r += nthreads) cls_acc += cls_rows[r];

    // box smooth-L1 sum
    float box_acc = 0.0f;
    int nb = num_pos * 4;
    for (int k = tid; k < nb; k += nthreads) {
        int i = k >> 2;
        int j = k & 3;
        float pred = box_regression[(size_t)i * (C * 4) + label[i] * 4 + j];
        float d = fabsf(pred - regression_target[k]);
        box_acc += (d < 1.0f) ? 0.5f * d * d : d - 0.5f;
    }

    // segment sums (shared atomics; error << tolerance)
    for (int r = tid; r < R; r += nthreads) {
        int g = matched_idx[r];
        atomicAdd(&bins[g], per_roi[r]);
        atomicAdd(&cnts[g], 1.0f);
    }

    // block-reduce cls_acc and box_acc
    #pragma unroll
    for (int o = 16; o; o >>= 1) {
        cls_acc += __shfl_xor_sync(0xFFFFFFFFu, cls_acc, o);
        box_acc += __shfl_xor_sync(0xFFFFFFFFu, box_acc, o);
    }
    int lane = tid & 31, w = tid >> 5;
    __shared__ float red2[8];
    if (lane == 0) { red[w] = cls_acc; red2[w] = box_acc; }
    __syncthreads();
    if (tid == 0) {
        float cs = 0.0f, bs = 0.0f;
        int nw = nthreads >> 5;
        for (int i = 0; i < nw; i++) { cs += red[i]; bs += red2[i]; }
        out[0] = cs / (float)R;
        out[1] = bs / (float)R;
    }
    __syncthreads();

    for (int g = tid; g < G; g += nthreads) {
        float c = cnts[g];
        out[2 + g] = (c > 0.0f) ? bins[g] / fmaxf(c, 1.0f) : 0.0f;
    }
}

// ---------------------------------------------------------------------------
// Launch
// ---------------------------------------------------------------------------
extern "C" void kernel_launch(void* const* d_in, const int* in_sizes, int n_in,
                              void* d_out, int out_size) {
    const float* class_logit       = (const float*)d_in[0];
    const float* box_regression    = (const float*)d_in[1];
    const float* regression_target = (const float*)d_in[2];
    const float* mask_logit        = (const float*)d_in[3];
    const float* proposal          = (const float*)d_in[4];
    const float* gt_mask           = (const float*)d_in[5];
    const int*   matched_idx       = (const int*)d_in[6];
    const int*   label             = (const int*)d_in[7];
    float* out = (float*)d_out;

    // Derive shapes
    int R = in_sizes[4] / 4;                         // proposal [R,4]
    int C = in_sizes[0] / R;                         // class_logit [R,C]
    int num_pos = in_sizes[2] / 4;                   // regression_target [P,4]
    long long mm = (long long)in_sizes[3] / ((long long)R * C);
    int Mo = (int)(sqrtf((float)mm) + 0.5f);         // mask_logit [R,C,Mo,Mo]
    int G = out_size - 2;                            // per_gt bins
    long long hw = (long long)in_sizes[5] / G;       // gt_mask [G,H,W]
    int Hh = (int)(sqrtf((float)hw) + 0.5f);
    int Ww = Hh;

    float* cls_scratch;
    float* roi_scratch;
    cudaGetSymbolAddress((void**)&cls_scratch, g_cls);
    cudaGetSymbolAddress((void**)&roi_scratch, g_per_roi);

    // Kernel 1: cls per-row (8 warps per 256-thread block)
    int rows_per_block = 256 / 32;
    int nblk1 = (R + rows_per_block - 1) / rows_per_block;
    cls_rows_kernel<<<nblk1, 256>>>(class_logit, label, cls_scratch, R, C);

    // Kernel 2: mask per-roi
    mask_kernel<<<R, 256>>>(mask_logit, proposal, gt_mask, matched_idx, label,
                            roi_scratch, C, Mo, Hh, Ww);

    // Kernel 3: finalize
    size_t shm = (size_t)(2 * G) * sizeof(float);
    finalize_kernel<<<1, 256, shm>>>(cls_scratch, box_regression, regression_target,
                                     roi_scratch, matched_idx, label, out,
                                     R, C, G, num_pos);
}

// round 2
// speedup vs baseline: 1.3200x; 1.3200x over previous
#include <cuda_runtime.h>
#include <cuda_bf16.h>
#include <math.h>

// Scratch (no device allocation allowed). Sized with headroom over R=2048.
__device__ float g_cls[4096];
__device__ float g_per_roi[4096];

// ---------------------------------------------------------------------------
// Fused kernel: one block (256 thr) per RoI.
//   - all warps: RoI-align bilinear target + BCE sum over P=Mo*Mo points
//   - warp 0: final block reduce of mask BCE  -> per_roi[r]
//   - warp 1: -log_softmax(class_logit[r])[label[r]] -> cls_out[r]
// MO > 0: compile-time Mo (fast path).  MO == 0: runtime Mo.
// ---------------------------------------------------------------------------
template<int MO>
__global__ void __launch_bounds__(256) fused_kernel(
        const float* __restrict__ class_logit,
        const float* __restrict__ mask_logit,
        const float* __restrict__ proposal,
        const float* __restrict__ gt_mask,
        const int* __restrict__ matched_idx,
        const int* __restrict__ label,
        float* __restrict__ cls_out,
        float* __restrict__ per_roi,
        int C, int Hh, int Ww, int Mo_rt) {
    const int Mo = (MO > 0) ? MO : Mo_rt;
    const int P  = Mo * Mo;
    int r    = blockIdx.x;
    int tid  = threadIdx.x;
    int lane = tid & 31;
    int w    = tid >> 5;
    __shared__ float sh[8];

    int lab = __ldg(&label[r]);
    int b   = __ldg(&matched_idx[r]);
    float4 box = *(const float4*)(proposal + (size_t)r * 4);
    float x1 = box.x, y1 = box.y, x2 = box.z, y2 = box.w;
    float invMo = 1.0f / (float)Mo;
    float sx = (x2 - x1) * invMo;
    float sy = (y2 - y1) * invMo;

    const float* sel = mask_logit + ((size_t)r * C + lab) * P;
    const float* fm  = gt_mask + (size_t)b * Hh * Ww;

    float acc  = 0.0f;   // sum of max(s,0) - s*t
    float prod = 1.0f;   // product of (1 + exp(-|s|)) over this thread's points

    const int ITERS = (MO > 0) ? ((MO * MO + 255) / 256) : ((P + 255) / 256);
    #pragma unroll
    for (int i = 0; i < ITERS; i++) {
        int p = tid + i * 256;
        if (p < P) {
            int iy = p / Mo;                 // compile-time Mo -> strength-reduced
            int ix = p - iy * Mo;
            float x = x1 + ((float)ix + 0.5f) * sx;
            float y = y1 + ((float)iy + 0.5f) * sy;
            float t = 0.0f;
            if (x > -1.0f && x < (float)Ww && y > -1.0f && y < (float)Hh) {
                float xc = fminf(fmaxf(x, 0.0f), (float)(Ww - 1));
                float yc = fminf(fmaxf(y, 0.0f), (float)(Hh - 1));
                int x0 = (int)xc;            // xc >= 0: trunc == floor
                int y0 = (int)yc;
                int xi = min(x0 + 1, Ww - 1);
                int yi = min(y0 + 1, Hh - 1);
                float lx = xc - (float)x0;
                float ly = yc - (float)y0;
                const float* r0 = fm + (size_t)y0 * Ww;
                const float* r1 = fm + (size_t)yi * Ww;
                float v00 = __ldg(r0 + x0);
                float v01 = __ldg(r0 + xi);
                float v10 = __ldg(r1 + x0);
                float v11 = __ldg(r1 + xi);
                float top = fmaf(lx, v01 - v00, v00);
                float bot = fmaf(lx, v11 - v10, v10);
                t = fmaf(ly, bot - top, top);
            }
            float s = __ldg(sel + p);
            acc  += fmaxf(s, 0.0f) - s * t;
            prod *= 1.0f + __expf(-fabsf(s));
        }
    }

    // product across 8-lane groups (<= 2^32, safe in fp32), one log per group
    #pragma unroll
    for (int o = 1; o < 8; o <<= 1) prod *= __shfl_xor_sync(0xFFFFFFFFu, prod, o);
    if ((lane & 7) == 0) acc += __logf(prod);

    #pragma unroll
    for (int o = 16; o; o >>= 1) acc += __shfl_xor_sync(0xFFFFFFFFu, acc, o);
    if (lane == 0) sh[w] = acc;
    __syncthreads();

    if (w == 0) {
        float v = (lane < 8) ? sh[lane] : 0.0f;
        #pragma unroll
        for (int o = 4; o; o >>= 1) v += __shfl_xor_sync(0xFFFFFFFFu, v, o);
        if (lane == 0) per_roi[r] = v / (float)P;
    } else if (w == 1) {
        // classification CE for this row, runs concurrently with warp 0's reduce
        const float* row = class_logit + (size_t)r * C;
        float mx = -INFINITY;
        for (int c = lane; c < C; c += 32) mx = fmaxf(mx, __ldg(row + c));
        #pragma unroll
        for (int o = 16; o; o >>= 1) mx = fmaxf(mx, __shfl_xor_sync(0xFFFFFFFFu, mx, o));
        float s2 = 0.0f;
        for (int c = lane; c < C; c += 32) s2 += __expf(__ldg(row + c) - mx);
        #pragma unroll
        for (int o = 16; o; o >>= 1) s2 += __shfl_xor_sync(0xFFFFFFFFu, s2, o);
        if (lane == 0) cls_out[r] = mx + __logf(s2) - __ldg(row + lab);
    }
}

// ---------------------------------------------------------------------------
// Finalize: 2 independent blocks.
//   block 0: cls mean (out[0]) + box smooth-L1 (out[1])
//   block 1: segment mean per gt (out[2..2+G))
// ---------------------------------------------------------------------------
__global__ void finalize_kernel(const float* __restrict__ cls_rows,
                                const float* __restrict__ box_regression,
                                const float* __restrict__ regression_target,
                                const float* __restrict__ per_roi,
                                const int* __restrict__ matched_idx,
                                const int* __restrict__ label,
                                float* __restrict__ out,
                                int R, int C, int G, int num_pos) {
    extern __shared__ float smem[];
    int tid = threadIdx.x;
    int nthreads = blockDim.x;
    int lane = tid & 31, w = tid >> 5;

    if (blockIdx.x == 0) {
        __shared__ float red[32], red2[32];
        float cls_acc = 0.0f;
        for (int r = tid; r < R; r += nthreads) cls_acc += cls_rows[r];
        float box_acc = 0.0f;
        int nb = num_pos * 4;
        for (int k = tid; k < nb; k += nthreads) {
            int i = k >> 2;
            int j = k & 3;
            float pred = box_regression[(size_t)i * (C * 4) + label[i] * 4 + j];
            float d = fabsf(pred - regression_target[k]);
            box_acc += (d < 1.0f) ? 0.5f * d * d : d - 0.5f;
        }
        #pragma unroll
        for (int o = 16; o; o >>= 1) {
            cls_acc += __shfl_xor_sync(0xFFFFFFFFu, cls_acc, o);
            box_acc += __shfl_xor_sync(0xFFFFFFFFu, box_acc, o);
        }
        if (lane == 0) { red[w] = cls_acc; red2[w] = box_acc; }
        __syncthreads();
        if (tid == 0) {
            float cs = 0.0f, bs = 0.0f;
            int nw = nthreads >> 5;
            for (int i = 0; i < nw; i++) { cs += red[i]; bs += red2[i]; }
            out[0] = cs / (float)R;
            out[1] = bs / (float)R;
        }
    } else {
        float* bins = smem;       // G
        float* cnts = smem + G;   // G
        for (int g = tid; g < G; g += nthreads) { bins[g] = 0.0f; cnts[g] = 0.0f; }
        __syncthreads();
        for (int r = tid; r < R; r += nthreads) {
            int g = matched_idx[r];
            atomicAdd(&bins[g], per_roi[r]);
            atomicAdd(&cnts[g], 1.0f);
        }
        __syncthreads();
        for (int g = tid; g < G; g += nthreads) {
            float c = cnts[g];
            out[2 + g] = (c > 0.0f) ? bins[g] / fmaxf(c, 1.0f) : 0.0f;
        }
    }
}

// ---------------------------------------------------------------------------
// Launch
// ---------------------------------------------------------------------------
extern "C" void kernel_launch(void* const* d_in, const int* in_sizes, int n_in,
                              void* d_out, int out_size) {
    const float* class_logit       = (const float*)d_in[0];
    const float* box_regression    = (const float*)d_in[1];
    const float* regression_target = (const float*)d_in[2];
    const float* mask_logit        = (const float*)d_in[3];
    const float* proposal          = (const float*)d_in[4];
    const float* gt_mask           = (const float*)d_in[5];
    const int*   matched_idx       = (const int*)d_in[6];
    const int*   label             = (const int*)d_in[7];
    float* out = (float*)d_out;

    // Derive shapes
    int R = in_sizes[4] / 4;                         // proposal [R,4]
    int C = in_sizes[0] / R;                         // class_logit [R,C]
    int num_pos = in_sizes[2] / 4;                   // regression_target [P,4]
    long long mm = (long long)in_sizes[3] / ((long long)R * C);
    int Mo = (int)(sqrtf((float)mm) + 0.5f);         // mask_logit [R,C,Mo,Mo]
    int G = out_size - 2;                            // per_gt bins
    long long hw = (long long)in_sizes[5] / G;       // gt_mask [G,H,W]
    int Hh = (int)(sqrtf((float)hw) + 0.5f);
    int Ww = Hh;

    float* cls_scratch;
    float* roi_scratch;
    cudaGetSymbolAddress((void**)&cls_scratch, g_cls);
    cudaGetSymbolAddress((void**)&roi_scratch, g_per_roi);

    if (Mo == 28) {
        fused_kernel<28><<<R, 256>>>(class_logit, mask_logit, proposal, gt_mask,
                                     matched_idx, label, cls_scratch, roi_scratch,
                                     C, Hh, Ww, Mo);
    } else {
        fused_kernel<0><<<R, 256>>>(class_logit, mask_logit, proposal, gt_mask,
                                    matched_idx, label, cls_scratch, roi_scratch,
                                    C, Hh, Ww, Mo);
    }

    size_t shm = (size_t)(2 * G) * sizeof(float);
    finalize_kernel<<<2, 512, shm>>>(cls_scratch, box_regression, regression_target,
                                     roi_scratch, matched_idx, label, out,
                                     R, C, G, num_pos);
}

// round 3
// speedup vs baseline: 1.4804x; 1.1215x over previous
#include <cuda_runtime.h>
#include <cuda_bf16.h>
#include <math.h>

// Global accumulators (zero-initialized at module load; the writer kernel
// re-zeroes them after each use, so every graph replay sees zeros).
__device__ float g_bins[128];
__device__ int   g_cnt[128];
__device__ float g_cls_sum;
__device__ float g_box_sum;

// ---------------------------------------------------------------------------
// Fused kernel: one block (256 thr) per RoI r.
//   warps 0-6 (tid 0..195 active): RoI-align bilinear target + BCE, float4 path
//   warp 7: cls CE for row r  (+ box smooth-L1 if r < num_pos)
//   block reduce -> atomicAdd into g_bins / g_cnt / g_cls_sum / g_box_sum
// ---------------------------------------------------------------------------
template<int MO>
__global__ void __launch_bounds__(256) fused_kernel(
        const float* __restrict__ class_logit,
        const float* __restrict__ box_regression,
        const float* __restrict__ regression_target,
        const float* __restrict__ mask_logit,
        const float* __restrict__ proposal,
        const float* __restrict__ gt_mask,
        const int* __restrict__ matched_idx,
        const int* __restrict__ label,
        int C, int Hh, int Ww, int Mo_rt, int num_pos) {
    const int Mo = (MO > 0) ? MO : Mo_rt;
    const int P  = Mo * Mo;
    int r    = blockIdx.x;
    int tid  = threadIdx.x;
    int lane = tid & 31;
    int w    = tid >> 5;
    __shared__ float sh[8];

    int lab = __ldg(&label[r]);
    int b   = __ldg(&matched_idx[r]);

    float acc = 0.0f;

    if (w == 7) {
        // ---- classification CE for this row ----
        const float* row = class_logit + (size_t)r * C;
        float mx = -INFINITY;
        for (int c = lane; c < C; c += 32) mx = fmaxf(mx, __ldg(row + c));
        #pragma unroll
        for (int o = 16; o; o >>= 1) mx = fmaxf(mx, __shfl_xor_sync(0xFFFFFFFFu, mx, o));
        float s2 = 0.0f;
        for (int c = lane; c < C; c += 32) s2 += __expf(__ldg(row + c) - mx);
        #pragma unroll
        for (int o = 16; o; o >>= 1) s2 += __shfl_xor_sync(0xFFFFFFFFu, s2, o);
        if (lane == 0) atomicAdd(&g_cls_sum, mx + __logf(s2) - __ldg(row + lab));

        // ---- box smooth-L1 for this row (if positive) ----
        if (r < num_pos) {
            float term = 0.0f;
            if (lane < 4) {
                float pred = __ldg(&box_regression[(size_t)r * (C * 4) + lab * 4 + lane]);
                float tgt  = __ldg(&regression_target[r * 4 + lane]);
                float d = fabsf(pred - tgt);
                term = (d < 1.0f) ? 0.5f * d * d : d - 0.5f;
            }
            #pragma unroll
            for (int o = 2; o; o >>= 1) term += __shfl_xor_sync(0xFFFFFFFFu, term, o);
            if (lane == 0) atomicAdd(&g_box_sum, term);
        }
        if (lane == 0) sh[7] = 0.0f;
    } else {
        // ---- mask BCE ----
        float4 box = *(const float4*)(proposal + (size_t)r * 4);
        float x1 = box.x, y1 = box.y, x2 = box.z, y2 = box.w;
        float invMo = 1.0f / (float)Mo;
        float sx = (x2 - x1) * invMo;
        float sy = (y2 - y1) * invMo;
        const float* sel = mask_logit + ((size_t)r * C + lab) * P;
        const float* fm  = gt_mask + (size_t)b * Hh * Ww;

        float prod = 1.0f;

        if (MO == 28) {
            // 196 float4 chunks; each chunk lies within one grid row (28/4=7)
            const int q = tid;                 // tid 0..195 active
            if (q < 196) {
                int iy  = q / 7;
                int ix0 = (q - iy * 7) << 2;
                float y = fmaf((float)iy + 0.5f, sy, y1);
                float4 s4 = __ldg((const float4*)sel + q);

                bool vy = (y > -1.0f) & (y < (float)Hh);
                float yc = fminf(fmaxf(y, 0.0f), (float)(Hh - 1));
                int y0 = (int)yc;
                int yi = min(y0 + 1, Hh - 1);
                float ly = yc - (float)y0;
                const float* r0 = fm + (size_t)y0 * Ww;
                const float* r1 = fm + (size_t)yi * Ww;

                #pragma unroll
                for (int j = 0; j < 4; j++) {
                    float s = (j == 0) ? s4.x : (j == 1) ? s4.y : (j == 2) ? s4.z : s4.w;
                    float x = fmaf((float)(ix0 + j) + 0.5f, sx, x1);
                    float t = 0.0f;
                    if (vy & (x > -1.0f) & (x < (float)Ww)) {
                        float xc = fminf(fmaxf(x, 0.0f), (float)(Ww - 1));
                        int x0 = (int)xc;
                        int xi = min(x0 + 1, Ww - 1);
                        float lx = xc - (float)x0;
                        float v00 = __ldg(r0 + x0);
                        float v01 = __ldg(r0 + xi);
                        float v10 = __ldg(r1 + x0);
                        float v11 = __ldg(r1 + xi);
                        float top = fmaf(lx, v01 - v00, v00);
                        float bot = fmaf(lx, v11 - v10, v10);
                        t = fmaf(ly, bot - top, top);
                    }
                    acc  += fmaxf(s, 0.0f) - s * t;
                    prod *= 1.0f + __expf(-fabsf(s));
                }
            }
        } else {
            // generic scalar path
            for (int p = tid; p < P; p += 224) {
                int iy = p / Mo;
                int ix = p - iy * Mo;
                float x = fmaf((float)ix + 0.5f, sx, x1);
                float y = fmaf((float)iy + 0.5f, sy, y1);
                float t = 0.0f;
                if (x > -1.0f && x < (float)Ww && y > -1.0f && y < (float)Hh) {
                    float xc = fminf(fmaxf(x, 0.0f), (float)(Ww - 1));
                    float yc = fminf(fmaxf(y, 0.0f), (float)(Hh - 1));
                    int x0 = (int)xc, y0 = (int)yc;
                    int xi = min(x0 + 1, Ww - 1);
                    int yi = min(y0 + 1, Hh - 1);
                    float lx = xc - (float)x0, ly = yc - (float)y0;
                    const float* r0 = fm + (size_t)y0 * Ww;
                    const float* r1 = fm + (size_t)yi * Ww;
                    float v00 = __ldg(r0 + x0), v01 = __ldg(r0 + xi);
                    float v10 = __ldg(r1 + x0), v11 = __ldg(r1 + xi);
                    float top = fmaf(lx, v01 - v00, v00);
                    float bot = fmaf(lx, v11 - v10, v10);
                    t = fmaf(ly, bot - top, top);
                }
                float s = __ldg(sel + p);
                acc  += fmaxf(s, 0.0f) - s * t;
                prod *= 1.0f + __expf(-fabsf(s));
            }
        }

        // product across 8-lane groups (each factor <= 2, <= 8 pts/thread -> safe)
        #pragma unroll
        for (int o = 1; o < 8; o <<= 1) prod *= __shfl_xor_sync(0xFFFFFFFFu, prod, o);
        if ((lane & 7) == 0) acc += __logf(prod);

        #pragma unroll
        for (int o = 16; o; o >>= 1) acc += __shfl_xor_sync(0xFFFFFFFFu, acc, o);
        if (lane == 0) sh[w] = acc;
    }
    __syncthreads();

    if (w == 0) {
        float v = (lane < 8) ? sh[lane] : 0.0f;
        #pragma unroll
        for (int o = 4; o; o >>= 1) v += __shfl_xor_sync(0xFFFFFFFFu, v, o);
        if (lane == 0) {
            atomicAdd(&g_bins[b], v / (float)P);
            atomicAdd(&g_cnt[b], 1);
        }
    }
}

// ---------------------------------------------------------------------------
// Writer: 1 block. Reads accumulators, writes all outputs, then resets the
// accumulators so the next graph replay starts from zero.
// ---------------------------------------------------------------------------
__global__ void writer_kernel(float* __restrict__ out, int R, int G) {
    int tid = threadIdx.x;
    if (tid == 0) out[0] = g_cls_sum / (float)R;
    if (tid == 1) out[1] = g_box_sum / (float)R;
    if (tid < G) {
        int c = g_cnt[tid];
        out[2 + tid] = (c > 0) ? g_bins[tid] / (float)c : 0.0f;
    }
    __syncthreads();
    if (tid == 0) { g_cls_sum = 0.0f; g_box_sum = 0.0f; }
    if (tid < 128) { g_bins[tid] = 0.0f; g_cnt[tid] = 0; }
}

// ---------------------------------------------------------------------------
// Launch
// ---------------------------------------------------------------------------
extern "C" void kernel_launch(void* const* d_in, const int* in_sizes, int n_in,
                              void* d_out, int out_size) {
    const float* class_logit       = (const float*)d_in[0];
    const float* box_regression    = (const float*)d_in[1];
    const float* regression_target = (const float*)d_in[2];
    const float* mask_logit        = (const float*)d_in[3];
    const float* proposal          = (const float*)d_in[4];
    const float* gt_mask           = (const float*)d_in[5];
    const int*   matched_idx       = (const int*)d_in[6];
    const int*   label             = (const int*)d_in[7];
    float* out = (float*)d_out;

    int R = in_sizes[4] / 4;                         // proposal [R,4]
    int C = in_sizes[0] / R;                         // class_logit [R,C]
    int num_pos = in_sizes[2] / 4;                   // regression_target [P,4]
    long long mm = (long long)in_sizes[3] / ((long long)R * C);
    int Mo = (int)(sqrtf((float)mm) + 0.5f);         // mask_logit [R,C,Mo,Mo]
    int G = out_size - 2;                            // per_gt bins
    long long hw = (long long)in_sizes[5] / G;       // gt_mask [G,H,W]
    int Hh = (int)(sqrtf((float)hw) + 0.5f);
    int Ww = Hh;

    if (Mo == 28) {
        fused_kernel<28><<<R, 256>>>(class_logit, box_regression, regression_target,
                                     mask_logit, proposal, gt_mask,
                                     matched_idx, label, C, Hh, Ww, Mo, num_pos);
    } else {
        fused_kernel<0><<<R, 256>>>(class_logit, box_regression, regression_target,
                                    mask_logit, proposal, gt_mask,
                                    matched_idx, label, C, Hh, Ww, Mo, num_pos);
    }
    writer_kernel<<<1, 128>>>(out, R, G);
}